// round 4
// baseline (speedup 1.0000x reference)
#include <cuda_runtime.h>
#include <cuda_fp16.h>
#include <cstdint>

// ============================================================================
// B=8, N=512, K=16, D=512
//   pre[b,n,k,f] = node@Wn + graph@Wg + locg@Wl + loc@Wloc + b1
//   score[b,n,k] = relu(pre) @ W2 + b2
// compute_100-safe path: fp16 mma.sync.m16n8k16 (f32 accum), ldmatrix, cp.async.
// ReLU is elementwise in f -> score splits over f-chunks -> partial sums.
// Grid: N-chunk on blockIdx.x (fast) so one A tile's 4 N-chunks share a wave
// and A streams from DRAM once, not 4x.
// ============================================================================

#define M_TILE   128
#define N_TILE   128
#define K_CHUNK  64
#define KCHUNKS  8          // 512 / 64

// dynamic smem layout
#define STG_BYTES   32768   // A 16KB fp16 + B 16KB fp16
#define SM_EXTRA    65536   // after 2 stages
#define SM_SBASE    (SM_EXTRA)          // 4KB: 8 base rows x 128 cols (mode1)
#define SM_SVEC     (SM_EXTRA + 4096)   // 512B: w2 chunk / baseb chunk
#define SM_RED      (SM_EXTRA + 4608)   // 1KB: cross-warp row partials
#define SMEM_BYTES  (SM_EXTRA + 4608 + 1024)

// ---------------------------------------------------------------------------
// Scratch (__device__ globals; no allocations allowed)
// ---------------------------------------------------------------------------
__device__ __half g_WTn[512 * 512];    // Wn^T  [f][d] fp16
__device__ __half g_WTloc[512 * 512];  // Wloc^T[f][d] fp16
__device__ float  g_baseb[8 * 512];    // graph@Wg + locg@Wl + b1
__device__ float  g_base[4096 * 512];  // node@Wn + baseb, per (b,n) row
__device__ float  g_part[4][65536];    // partial scores per f-chunk

// ---------------------------------------------------------------------------
// helpers
// ---------------------------------------------------------------------------
__device__ __forceinline__ uint32_t smem_u32(const void* p) {
    uint32_t a;
    asm("{ .reg .u64 t; cvta.to.shared.u64 t, %1; cvt.u32.u64 %0, t; }" : "=r"(a) : "l"(p));
    return a;
}

__device__ __forceinline__ void ldsm4(uint32_t* r, uint32_t addr) {
    asm volatile("ldmatrix.sync.aligned.m8n8.x4.shared.b16 {%0,%1,%2,%3}, [%4];"
                 : "=r"(r[0]), "=r"(r[1]), "=r"(r[2]), "=r"(r[3]) : "r"(addr));
}

__device__ __forceinline__ void mma16816(float* d, const uint32_t* a, const uint32_t* b) {
    asm volatile(
        "mma.sync.aligned.m16n8k16.row.col.f32.f16.f16.f32 "
        "{%0,%1,%2,%3}, {%4,%5,%6,%7}, {%8,%9}, {%0,%1,%2,%3};"
        : "+f"(d[0]), "+f"(d[1]), "+f"(d[2]), "+f"(d[3])
        : "r"(a[0]), "r"(a[1]), "r"(a[2]), "r"(a[3]), "r"(b[0]), "r"(b[1]));
}

#define CP_ASYNC16(dst, src) \
    asm volatile("cp.async.cg.shared.global [%0], [%1], 16;" :: "r"(dst), "l"(src))
#define CP_COMMIT()  asm volatile("cp.async.commit_group;")
#define CP_WAIT0()   asm volatile("cp.async.wait_group 0;")

// ---------------------------------------------------------------------------
// Kernel 1: transpose + fp16-convert Wn (W1 rows 0..511), Wloc (rows 1536..2047)
// ---------------------------------------------------------------------------
__global__ void transpose_kernel(const float* __restrict__ W1) {
    __shared__ float t[32][33];
    int which = blockIdx.z;
    const float* src = W1 + (which ? 1536 * 512 : 0);
    __half* dst = which ? g_WTloc : g_WTn;
    int d0 = blockIdx.x * 32, f0 = blockIdx.y * 32;
    int tx = threadIdx.x, ty = threadIdx.y;  // (32, 8)
#pragma unroll
    for (int i = 0; i < 32; i += 8)
        t[ty + i][tx] = src[(size_t)(d0 + ty + i) * 512 + f0 + tx];
    __syncthreads();
#pragma unroll
    for (int i = 0; i < 32; i += 8)
        dst[(size_t)(f0 + ty + i) * 512 + d0 + tx] = __float2half_rn(t[tx][ty + i]);
}

// ---------------------------------------------------------------------------
// Kernel 2: base_b[b,f] = b1[f] + graph[b]@Wg + locg[b]@Wl   (exact fp32)
// ---------------------------------------------------------------------------
__global__ void baseb_kernel(const float* __restrict__ graph,
                             const float* __restrict__ locg,
                             const float* __restrict__ W1,
                             const float* __restrict__ b1) {
    __shared__ float sg[512], sl[512];
    int b = blockIdx.x, t = threadIdx.x;
    for (int i = t; i < 512; i += 64) {
        sg[i] = graph[b * 512 + i];
        sl[i] = locg[b * 512 + i];
    }
    __syncthreads();
    int f = blockIdx.y * 64 + t;
    const float* Wg = W1 + (size_t)512 * 512 + f;
    const float* Wl = W1 + (size_t)1024 * 512 + f;
    float acc = b1[f];
#pragma unroll 8
    for (int d = 0; d < 512; ++d)
        acc += sg[d] * Wg[(size_t)d * 512] + sl[d] * Wl[(size_t)d * 512];
    g_baseb[b * 512 + f] = acc;
}

// ---------------------------------------------------------------------------
// Kernel 3/4: fp16 mma.sync GEMM, CTA tile 128(M) x 128(N), K=512.
// MODE 0: A=node (M=4096),  B=WTn;   epi: g_base = acc + baseb[b][fchunk]
// MODE 1: A=loc  (M=65536), B=WTloc; epi: g_part[nc] = sum_f relu(acc+base)*w2
// 256 threads = 8 warps as 4(M) x 2(N); warp tile 32x64.
// blockIdx.x = N-chunk (0..3), blockIdx.y = M-tile.
// ---------------------------------------------------------------------------
template <int MODE>
__global__ void __launch_bounds__(256)
gemm_kernel(const float* __restrict__ A, const float* __restrict__ W2) {
    extern __shared__ char smem[];
    const uint32_t sb = smem_u32(smem);
    const int tid = threadIdx.x;
    const int lane = tid & 31, wid = tid >> 5;
    const int wm = wid & 3, wn = wid >> 2;
    const int m0 = blockIdx.y * M_TILE;
    const int nc = blockIdx.x;
    const int n0 = nc * N_TILE;
    const __half* BT = (MODE == 0) ? g_WTn : g_WTloc;

    float* sbase = (float*)(smem + SM_SBASE);
    float* svec  = (float*)(smem + SM_SVEC);
    float* red   = (float*)(smem + SM_RED);

    // preload epilogue data (independent of mainloop)
    if (MODE == 1) {
        const float* gb = g_base + (size_t)(m0 >> 4) * 512 + n0;  // 8 rows x 128
        for (int i = tid; i < 1024; i += 256) {
            int r = i >> 7, c = i & 127;
            sbase[i] = gb[(size_t)r * 512 + c];
        }
        if (tid < 128) svec[tid] = W2[n0 + tid];
    } else {
        if (tid < 128) svec[tid] = g_baseb[(m0 >> 9) * 512 + n0 + tid];
    }

    const float*  gA = A + (size_t)m0 * 512;
    const __half* gB = BT + (size_t)n0 * 512;

    // per-thread load indices
    const int ar = (tid >> 4), ac4 = (tid & 15);       // A: +i*16 rows per iter
    const int br = (tid >> 3), bc16 = (tid & 7);       // B: +i*32 rows per iter

    float4 va[8];

    auto ldA = [&](int c) {
        const float* p = gA + c * K_CHUNK;
#pragma unroll
        for (int i = 0; i < 8; i++) {
            int r = ar + i * 16;
            va[i] = *(const float4*)(p + (size_t)r * 512 + ac4 * 4);
        }
    };
    auto stA = [&](uint32_t sA) {
#pragma unroll
        for (int i = 0; i < 8; i++) {
            int r = ar + i * 16;
            uint32_t ad = sA + r * 128 + ((ac4 * 8) ^ ((r & 7) * 16));
            __half2 h0 = __floats2half2_rn(va[i].x, va[i].y);
            __half2 h1 = __floats2half2_rn(va[i].z, va[i].w);
            uint32_t u0 = *(uint32_t*)&h0, u1 = *(uint32_t*)&h1;
            asm volatile("st.shared.v2.b32 [%0], {%1,%2};" :: "r"(ad), "r"(u0), "r"(u1));
        }
    };
    auto cpB = [&](int c, uint32_t sB) {
        const __half* p = gB + c * K_CHUNK;
#pragma unroll
        for (int i = 0; i < 4; i++) {
            int r = br + i * 32;
            uint32_t dst = sB + r * 128 + ((bc16 * 16) ^ ((r & 7) * 16));
            CP_ASYNC16(dst, p + (size_t)r * 512 + bc16 * 8);
        }
        CP_COMMIT();
    };

    // ldmatrix lane address precompute
    uint32_t aRB[2], aXO[2];
    const uint32_t aSel = (lane >> 4) * 16;
#pragma unroll
    for (int i = 0; i < 2; i++) {
        int r = wm * 32 + i * 16 + (lane & 15);
        aRB[i] = r * 128;
        aXO[i] = (r & 7) * 16;
    }
    uint32_t bRB[4], bXO[4];
    const uint32_t bSel = ((lane >> 3) & 1) * 16;
#pragma unroll
    for (int j = 0; j < 4; j++) {
        int r = wn * 64 + j * 16 + ((lane >> 4) << 3) + (lane & 7);
        bRB[j] = r * 128;
        bXO[j] = (r & 7) * 16;
    }

    float acc[2][8][4];
#pragma unroll
    for (int i = 0; i < 2; i++)
#pragma unroll
        for (int j = 0; j < 8; j++)
#pragma unroll
            for (int q = 0; q < 4; q++) acc[i][j][q] = 0.f;

    // prologue
    ldA(0);
    cpB(0, sb + 16384);
    stA(sb);
    CP_WAIT0();
    __syncthreads();

    int buf = 0;
#pragma unroll 1
    for (int c = 0; c < KCHUNKS; ++c) {
        const uint32_t sA = sb + buf * STG_BYTES;
        const uint32_t sBs = sA + 16384;
        const uint32_t oA = sb + (buf ^ 1) * STG_BYTES;
        if (c + 1 < KCHUNKS) {
            ldA(c + 1);               // LDGs in flight under the mma below
            cpB(c + 1, oA + 16384);
        }
#pragma unroll
        for (int ks = 0; ks < 4; ks++) {
            uint32_t af[2][4], bf[4][4];
            const uint32_t kc = ks * 32;
#pragma unroll
            for (int i = 0; i < 2; i++)
                ldsm4(af[i], sA + aRB[i] + ((kc | aSel) ^ aXO[i]));
#pragma unroll
            for (int j = 0; j < 4; j++)
                ldsm4(bf[j], sBs + bRB[j] + ((kc | bSel) ^ bXO[j]));
#pragma unroll
            for (int i = 0; i < 2; i++)
#pragma unroll
                for (int j = 0; j < 8; j++)
                    mma16816(acc[i][j], af[i], &bf[j >> 1][(j & 1) * 2]);
        }
        if (c + 1 < KCHUNKS) {
            stA(oA);
            CP_WAIT0();
        }
        __syncthreads();
        buf ^= 1;
    }

    // ---------------- epilogue ----------------
    const int t4 = lane >> 2;
    if (MODE == 0) {
#pragma unroll
        for (int i = 0; i < 2; i++) {
            int rL = wm * 32 + i * 16 + t4;
#pragma unroll
            for (int j = 0; j < 8; j++) {
                int c0 = wn * 64 + j * 8 + 2 * (lane & 3);
                float b0 = svec[c0], b1v = svec[c0 + 1];
                float2 v0 = make_float2(acc[i][j][0] + b0, acc[i][j][1] + b1v);
                float2 v1 = make_float2(acc[i][j][2] + b0, acc[i][j][3] + b1v);
                *(float2*)(g_base + (size_t)(m0 + rL) * 512 + n0 + c0) = v0;
                *(float2*)(g_base + (size_t)(m0 + rL + 8) * 512 + n0 + c0) = v1;
            }
        }
    } else {
        float psum[4] = {0.f, 0.f, 0.f, 0.f};
#pragma unroll
        for (int i = 0; i < 2; i++) {
            int rL0 = wm * 32 + i * 16 + t4;
            int br0 = rL0 >> 4;
            int br1 = (rL0 + 8) >> 4;
#pragma unroll
            for (int j = 0; j < 8; j++) {
                int c0 = wn * 64 + j * 8 + 2 * (lane & 3);
                float w0 = svec[c0], w1 = svec[c0 + 1];
                float b00 = sbase[br0 * 128 + c0], b01 = sbase[br0 * 128 + c0 + 1];
                float b10 = sbase[br1 * 128 + c0], b11 = sbase[br1 * 128 + c0 + 1];
                psum[i * 2 + 0] += fmaxf(acc[i][j][0] + b00, 0.f) * w0
                                 + fmaxf(acc[i][j][1] + b01, 0.f) * w1;
                psum[i * 2 + 1] += fmaxf(acc[i][j][2] + b10, 0.f) * w0
                                 + fmaxf(acc[i][j][3] + b11, 0.f) * w1;
            }
        }
#pragma unroll
        for (int ii = 0; ii < 4; ii++) {
            psum[ii] += __shfl_xor_sync(0xffffffffu, psum[ii], 1);
            psum[ii] += __shfl_xor_sync(0xffffffffu, psum[ii], 2);
        }
        if ((lane & 3) == 0) {
#pragma unroll
            for (int ii = 0; ii < 4; ii++) {
                int row = wm * 32 + (ii >> 1) * 16 + (ii & 1) * 8 + t4;
                red[wn * 128 + row] = psum[ii];
            }
        }
        __syncthreads();
        if (tid < 128)
            g_part[nc][m0 + tid] = red[tid] + red[128 + tid];
    }
}

// ---------------------------------------------------------------------------
// Kernel 5: out = sum of 4 partials + b2
// ---------------------------------------------------------------------------
__global__ void reduce_kernel(const float* __restrict__ b2, float* __restrict__ out) {
    int i = blockIdx.x * 256 + threadIdx.x;
    out[i] = g_part[0][i] + g_part[1][i] + g_part[2][i] + g_part[3][i] + b2[0];
}

// ---------------------------------------------------------------------------
// Launch
// ---------------------------------------------------------------------------
extern "C" void kernel_launch(void* const* d_in, const int* in_sizes, int n_in,
                              void* d_out, int out_size) {
    const float* node  = (const float*)d_in[0];  // (8, 512, 512)
    const float* loc   = (const float*)d_in[1];  // (8, 512, 16, 512)
    const float* graph = (const float*)d_in[2];  // (8, 512)
    const float* locg  = (const float*)d_in[3];  // (8, 512)
    const float* W1    = (const float*)d_in[4];  // (2048, 512)
    const float* b1    = (const float*)d_in[5];  // (512,)
    const float* W2    = (const float*)d_in[6];  // (512, 1)
    const float* b2    = (const float*)d_in[7];  // (1,)
    float* out = (float*)d_out;                  // (8, 8192)
    (void)in_sizes; (void)n_in; (void)out_size;

    cudaFuncSetAttribute(gemm_kernel<0>, cudaFuncAttributeMaxDynamicSharedMemorySize, SMEM_BYTES);
    cudaFuncSetAttribute(gemm_kernel<1>, cudaFuncAttributeMaxDynamicSharedMemorySize, SMEM_BYTES);

    transpose_kernel<<<dim3(16, 16, 2), dim3(32, 8)>>>(W1);
    baseb_kernel<<<dim3(8, 8), 64>>>(graph, locg, W1, b1);
    gemm_kernel<0><<<dim3(4, 32), 256, SMEM_BYTES>>>(node, nullptr);
    gemm_kernel<1><<<dim3(4, 512), 256, SMEM_BYTES>>>(loc, W2);
    reduce_kernel<<<256, 256>>>(b2, out);
}

// round 6
// speedup vs baseline: 1.2412x; 1.2412x over previous
#include <cuda_runtime.h>
#include <cuda_fp16.h>
#include <cstdint>

// ============================================================================
// B=8, N=512, K=16, D=512
//   pre[b,n,k,f] = node@Wn + graph@Wg + locg@Wl + loc@Wloc + b1
//   score[b,n,k] = relu(pre) @ W2 + b2
// fp16 mma.sync m16n8k16 (f32 accum). CTA tile 128x256, warp tile 64x64
// (8 warps as 2M x 4N) -> 128 B ldsm traffic per mma -> tensor-bound.
// ============================================================================

#define M_TILE   128
#define N_TILE   256
#define K_CHUNK  64
#define KCHUNKS  8          // 512 / 64

// dynamic smem layout
#define STG_BYTES   49152   // A 16KB fp16 + B 32KB fp16
#define SM_EXTRA    98304   // after 2 stages
#define SM_SBASE    (SM_EXTRA)          // 8KB: 8 base rows x 256 cols (mode1)
#define SM_SVEC     (SM_EXTRA + 8192)   // 1KB: w2 chunk / baseb chunk
#define SM_RED      (SM_EXTRA + 9216)   // 2KB: cross-warp row partials
#define SMEM_BYTES  (SM_EXTRA + 9216 + 2048)   // 109568

// ---------------------------------------------------------------------------
// Scratch (__device__ globals; no allocations allowed)
// ---------------------------------------------------------------------------
__device__ __half g_WTn[512 * 512];      // Wn^T  [f][d] fp16
__device__ __half g_WTloc[512 * 512];    // Wloc^T[f][d] fp16
__device__ float  g_basebp[8][8][512];   // [dsplit][b][f] partials (no b1)
__device__ float  g_base[4096 * 512];    // node@Wn + baseb + b1, per (b,n)
__device__ float  g_part[2][65536];      // partial scores per f-chunk

// ---------------------------------------------------------------------------
// helpers
// ---------------------------------------------------------------------------
__device__ __forceinline__ uint32_t smem_u32(const void* p) {
    uint32_t a;
    asm("{ .reg .u64 t; cvta.to.shared.u64 t, %1; cvt.u32.u64 %0, t; }" : "=r"(a) : "l"(p));
    return a;
}

__device__ __forceinline__ void ldsm4(uint32_t* r, uint32_t addr) {
    asm volatile("ldmatrix.sync.aligned.m8n8.x4.shared.b16 {%0,%1,%2,%3}, [%4];"
                 : "=r"(r[0]), "=r"(r[1]), "=r"(r[2]), "=r"(r[3]) : "r"(addr));
}

__device__ __forceinline__ void mma16816(float* d, const uint32_t* a, const uint32_t* b) {
    asm volatile(
        "mma.sync.aligned.m16n8k16.row.col.f32.f16.f16.f32 "
        "{%0,%1,%2,%3}, {%4,%5,%6,%7}, {%8,%9}, {%0,%1,%2,%3};"
        : "+f"(d[0]), "+f"(d[1]), "+f"(d[2]), "+f"(d[3])
        : "r"(a[0]), "r"(a[1]), "r"(a[2]), "r"(a[3]), "r"(b[0]), "r"(b[1]));
}

#define CP_ASYNC16(dst, src) \
    asm volatile("cp.async.cg.shared.global [%0], [%1], 16;" :: "r"(dst), "l"(src))
#define CP_COMMIT()  asm volatile("cp.async.commit_group;")
#define CP_WAIT0()   asm volatile("cp.async.wait_group 0;")

// ---------------------------------------------------------------------------
// prep kernel: blocks 0..511 transpose+convert Wn / Wloc; blocks 512..575
// compute baseb partials over 64-d slices (deterministic, no atomics).
// 256 threads per block.
// ---------------------------------------------------------------------------
__global__ void prep_kernel(const float* __restrict__ W1,
                            const float* __restrict__ graph,
                            const float* __restrict__ locg) {
    __shared__ float sh[32 * 33];
    int bid = blockIdx.x;
    int tid = threadIdx.x;
    if (bid < 512) {
        int which = bid >> 8;
        int tile = bid & 255;
        const float* src = W1 + (which ? 1536 * 512 : 0);
        __half* dst = which ? g_WTloc : g_WTn;
        int d0 = (tile & 15) * 32, f0 = (tile >> 4) * 32;
        int tx = tid & 31, ty = tid >> 5;  // (32, 8)
#pragma unroll
        for (int i = 0; i < 32; i += 8)
            sh[(ty + i) * 33 + tx] = src[(size_t)(d0 + ty + i) * 512 + f0 + tx];
        __syncthreads();
#pragma unroll
        for (int i = 0; i < 32; i += 8)
            dst[(size_t)(f0 + ty + i) * 512 + d0 + tx] = __float2half_rn(sh[tx * 33 + ty + i]);
    } else {
        int idx = bid - 512;            // 0..63
        int b = idx >> 3, ds = idx & 7; // d-range ds*64..+64
        float* sg = sh;                 // 64 floats
        float* sl = sh + 64;
        if (tid < 64) {
            sg[tid] = graph[b * 512 + ds * 64 + tid];
            sl[tid] = locg[b * 512 + ds * 64 + tid];
        }
        __syncthreads();
        const float* Wg = W1 + (size_t)512 * 512;
        const float* Wl = W1 + (size_t)1024 * 512;
        float a0 = 0.f, a1 = 0.f;
#pragma unroll 4
        for (int d = 0; d < 64; ++d) {
            size_t row = (size_t)(ds * 64 + d) * 512;
            float g = sg[d], l = sl[d];
            a0 += g * Wg[row + tid] + l * Wl[row + tid];
            a1 += g * Wg[row + tid + 256] + l * Wl[row + tid + 256];
        }
        g_basebp[ds][b][tid] = a0;
        g_basebp[ds][b][tid + 256] = a1;
    }
}

// ---------------------------------------------------------------------------
// gemm kernel: fp16 mma.sync, CTA tile 128(M) x 256(N), K=512.
// 256 threads = 8 warps as 2(M) x 4(N); warp tile 64x64.
// MODE 0: A=node (M=4096),  B=WTn;   epi: g_base = acc + (b1 + sum basebp)
// MODE 1: A=loc  (M=65536), B=WTloc; epi: g_part[nc] = sum_f relu(acc+base)*w2
// blockIdx.x = N-chunk (0..1), blockIdx.y = M-tile.
// ---------------------------------------------------------------------------
template <int MODE>
__global__ void __launch_bounds__(256)
gemm_kernel(const float* __restrict__ A, const float* __restrict__ W2,
            const float* __restrict__ b1) {
    extern __shared__ char smem[];
    const uint32_t sb = smem_u32(smem);
    const int tid = threadIdx.x;
    const int lane = tid & 31, wid = tid >> 5;
    const int wm = wid & 1, wn = wid >> 1;     // 2(M) x 4(N)
    const int m0 = blockIdx.y * M_TILE;
    const int nc = blockIdx.x;
    const int n0 = nc * N_TILE;
    const __half* BT = (MODE == 0) ? g_WTn : g_WTloc;

    float* sbase = (float*)(smem + SM_SBASE);
    float* svec  = (float*)(smem + SM_SVEC);
    float* red   = (float*)(smem + SM_RED);

    // preload epilogue data (independent of mainloop)
    if (MODE == 1) {
        const float* gb = g_base + (size_t)(m0 >> 4) * 512 + n0;  // 8 rows x 256
        for (int i = tid; i < 2048; i += 256) {
            int r = i >> 8, c = i & 255;
            sbase[i] = gb[(size_t)r * 512 + c];
        }
        if (tid < 256) svec[tid] = W2[n0 + tid];
    } else {
        int b = m0 >> 9;
        float v = b1[n0 + tid];
#pragma unroll
        for (int s = 0; s < 8; s++) v += g_basebp[s][b][n0 + tid];
        svec[tid] = v;
    }

    const float*  gA = A + (size_t)m0 * 512;
    const __half* gB = BT + (size_t)n0 * 512;

    // per-thread load indices
    const int ar = (tid >> 4), ac4 = (tid & 15);   // A: 16 rows/iter, 8 iters
    const int br = (tid >> 3), bc16 = (tid & 7);   // B: 32 rows/iter, 8 iters

    float4 va[8];

    auto ldA = [&](int c) {
        const float* p = gA + c * K_CHUNK;
#pragma unroll
        for (int i = 0; i < 8; i++) {
            int r = ar + i * 16;
            va[i] = *(const float4*)(p + (size_t)r * 512 + ac4 * 4);
        }
    };
    auto stA = [&](uint32_t sA) {
#pragma unroll
        for (int i = 0; i < 8; i++) {
            int r = ar + i * 16;
            uint32_t ad = sA + r * 128 + ((ac4 * 8) ^ ((r & 7) * 16));
            __half2 h0 = __floats2half2_rn(va[i].x, va[i].y);
            __half2 h1 = __floats2half2_rn(va[i].z, va[i].w);
            uint32_t u0 = *(uint32_t*)&h0, u1 = *(uint32_t*)&h1;
            asm volatile("st.shared.v2.b32 [%0], {%1,%2};" :: "r"(ad), "r"(u0), "r"(u1));
        }
    };
    auto cpB = [&](int c, uint32_t sB) {
        const __half* p = gB + c * K_CHUNK;
#pragma unroll
        for (int i = 0; i < 8; i++) {
            int r = br + i * 32;
            uint32_t dst = sB + r * 128 + ((bc16 * 16) ^ ((r & 7) * 16));
            CP_ASYNC16(dst, p + (size_t)r * 512 + bc16 * 8);
        }
        CP_COMMIT();
    };

    // ldmatrix lane address precompute
    uint32_t aRB[4], aXO[4];
    const uint32_t aSel = (lane >> 4) * 16;
#pragma unroll
    for (int i = 0; i < 4; i++) {
        int r = wm * 64 + i * 16 + (lane & 15);
        aRB[i] = r * 128;
        aXO[i] = (r & 7) * 16;
    }
    uint32_t bRB[4], bXO[4];
    const uint32_t bSel = ((lane >> 3) & 1) * 16;
#pragma unroll
    for (int j = 0; j < 4; j++) {
        int r = wn * 64 + j * 16 + ((lane >> 4) << 3) + (lane & 7);
        bRB[j] = r * 128;
        bXO[j] = (r & 7) * 16;
    }

    float acc[4][8][4];
#pragma unroll
    for (int i = 0; i < 4; i++)
#pragma unroll
        for (int j = 0; j < 8; j++)
#pragma unroll
            for (int q = 0; q < 4; q++) acc[i][j][q] = 0.f;

    // prologue
    ldA(0);
    cpB(0, sb + 16384);
    stA(sb);
    CP_WAIT0();
    __syncthreads();

    int buf = 0;
#pragma unroll 1
    for (int c = 0; c < KCHUNKS; ++c) {
        const uint32_t sA = sb + buf * STG_BYTES;
        const uint32_t sBs = sA + 16384;
        const uint32_t oA = sb + (buf ^ 1) * STG_BYTES;
        if (c + 1 < KCHUNKS) {
            ldA(c + 1);               // LDGs in flight under the mma below
            cpB(c + 1, oA + 16384);
        }
#pragma unroll
        for (int ks = 0; ks < 4; ks++) {
            uint32_t af[4][4], bf[4][4];
            const uint32_t kc = ks * 32;
#pragma unroll
            for (int i = 0; i < 4; i++)
                ldsm4(af[i], sA + aRB[i] + ((kc | aSel) ^ aXO[i]));
#pragma unroll
            for (int j = 0; j < 4; j++)
                ldsm4(bf[j], sBs + bRB[j] + ((kc | bSel) ^ bXO[j]));
#pragma unroll
            for (int i = 0; i < 4; i++)
#pragma unroll
                for (int j = 0; j < 8; j++)
                    mma16816(acc[i][j], af[i], &bf[j >> 1][(j & 1) * 2]);
        }
        if (c + 1 < KCHUNKS) {
            stA(oA);
            CP_WAIT0();
        }
        __syncthreads();
        buf ^= 1;
    }

    // ---------------- epilogue ----------------
    const int t4 = lane >> 2;
    if (MODE == 0) {
#pragma unroll
        for (int i = 0; i < 4; i++) {
            int rL = wm * 64 + i * 16 + t4;
#pragma unroll
            for (int j = 0; j < 8; j++) {
                int c0 = wn * 64 + j * 8 + 2 * (lane & 3);
                float b0 = svec[c0], b1v = svec[c0 + 1];
                float2 v0 = make_float2(acc[i][j][0] + b0, acc[i][j][1] + b1v);
                float2 v1 = make_float2(acc[i][j][2] + b0, acc[i][j][3] + b1v);
                *(float2*)(g_base + (size_t)(m0 + rL) * 512 + n0 + c0) = v0;
                *(float2*)(g_base + (size_t)(m0 + rL + 8) * 512 + n0 + c0) = v1;
            }
        }
    } else {
        float psum[8];
#pragma unroll
        for (int ii = 0; ii < 8; ii++) psum[ii] = 0.f;
#pragma unroll
        for (int i = 0; i < 4; i++) {
            int rL0 = wm * 64 + i * 16 + t4;
            int br0 = rL0 >> 4;
            int br1 = (rL0 + 8) >> 4;
#pragma unroll
            for (int j = 0; j < 8; j++) {
                int c0 = wn * 64 + j * 8 + 2 * (lane & 3);
                float w0 = svec[c0], w1 = svec[c0 + 1];
                float b00 = sbase[br0 * 256 + c0], b01 = sbase[br0 * 256 + c0 + 1];
                float b10 = sbase[br1 * 256 + c0], b11 = sbase[br1 * 256 + c0 + 1];
                psum[i * 2 + 0] += fmaxf(acc[i][j][0] + b00, 0.f) * w0
                                 + fmaxf(acc[i][j][1] + b01, 0.f) * w1;
                psum[i * 2 + 1] += fmaxf(acc[i][j][2] + b10, 0.f) * w0
                                 + fmaxf(acc[i][j][3] + b11, 0.f) * w1;
            }
        }
#pragma unroll
        for (int ii = 0; ii < 8; ii++) {
            psum[ii] += __shfl_xor_sync(0xffffffffu, psum[ii], 1);
            psum[ii] += __shfl_xor_sync(0xffffffffu, psum[ii], 2);
        }
        if ((lane & 3) == 0) {
#pragma unroll
            for (int ii = 0; ii < 8; ii++) {
                int row = wm * 64 + (ii >> 1) * 16 + (ii & 1) * 8 + t4;
                red[wn * 128 + row] = psum[ii];
            }
        }
        __syncthreads();
        if (tid < 128)
            g_part[nc][m0 + tid] = red[tid] + red[128 + tid] + red[256 + tid] + red[384 + tid];
    }
}

// ---------------------------------------------------------------------------
// reduce: out = sum of 2 partials + b2
// ---------------------------------------------------------------------------
__global__ void reduce_kernel(const float* __restrict__ b2, float* __restrict__ out) {
    int i = blockIdx.x * 256 + threadIdx.x;
    out[i] = g_part[0][i] + g_part[1][i] + b2[0];
}

// ---------------------------------------------------------------------------
// Launch
// ---------------------------------------------------------------------------
extern "C" void kernel_launch(void* const* d_in, const int* in_sizes, int n_in,
                              void* d_out, int out_size) {
    const float* node  = (const float*)d_in[0];  // (8, 512, 512)
    const float* loc   = (const float*)d_in[1];  // (8, 512, 16, 512)
    const float* graph = (const float*)d_in[2];  // (8, 512)
    const float* locg  = (const float*)d_in[3];  // (8, 512)
    const float* W1    = (const float*)d_in[4];  // (2048, 512)
    const float* b1    = (const float*)d_in[5];  // (512,)
    const float* W2    = (const float*)d_in[6];  // (512, 1)
    const float* b2    = (const float*)d_in[7];  // (1,)
    float* out = (float*)d_out;                  // (8, 8192)
    (void)in_sizes; (void)n_in; (void)out_size;

    cudaFuncSetAttribute(gemm_kernel<0>, cudaFuncAttributeMaxDynamicSharedMemorySize, SMEM_BYTES);
    cudaFuncSetAttribute(gemm_kernel<1>, cudaFuncAttributeMaxDynamicSharedMemorySize, SMEM_BYTES);

    prep_kernel<<<576, 256>>>(W1, graph, locg);
    gemm_kernel<0><<<dim3(2, 32), 256, SMEM_BYTES>>>(node, nullptr, b1);
    gemm_kernel<1><<<dim3(2, 512), 256, SMEM_BYTES>>>(loc, W2, nullptr);
    reduce_kernel<<<256, 256>>>(b2, out);
}

// round 7
// speedup vs baseline: 1.2422x; 1.0008x over previous
#include <cuda_runtime.h>
#include <cuda_fp16.h>
#include <cstdint>

// ============================================================================
// B=8, N=512, K=16, D=512
//   pre[b,n,k,f] = node@Wn + graph@Wg + locg@Wl + loc@Wloc + b1
//   score[b,n,k] = relu(pre) @ W2 + b2
// fp16 mma.sync m16n8k16 (f32 accum). CTA tile 128x256, warp tile 64x64
// (8 warps as 2M x 4N) -> 128 B ldsm traffic per mma -> tensor-bound.
// ============================================================================

#define M_TILE   128
#define N_TILE   256
#define K_CHUNK  64
#define KCHUNKS  8          // 512 / 64

// dynamic smem layout
#define STG_BYTES   49152   // A 16KB fp16 + B 32KB fp16
#define SM_EXTRA    98304   // after 2 stages
#define SM_SBASE    (SM_EXTRA)          // 8KB: 8 base rows x 256 cols (mode1)
#define SM_SVEC     (SM_EXTRA + 8192)   // 1KB: w2 chunk / baseb chunk
#define SM_RED      (SM_EXTRA + 9216)   // 2KB: cross-warp row partials
#define SMEM_BYTES  (SM_EXTRA + 9216 + 2048)   // 109568

// ---------------------------------------------------------------------------
// Scratch (__device__ globals; no allocations allowed)
// ---------------------------------------------------------------------------
__device__ __half g_WTn[512 * 512];      // Wn^T  [f][d] fp16
__device__ __half g_WTloc[512 * 512];    // Wloc^T[f][d] fp16
__device__ float  g_basebp[8][8][512];   // [dsplit][b][f] partials (no b1)
__device__ float  g_base[4096 * 512];    // node@Wn + baseb + b1, per (b,n)
__device__ float  g_part[2][65536];      // partial scores per f-chunk

// ---------------------------------------------------------------------------
// helpers
// ---------------------------------------------------------------------------
__device__ __forceinline__ uint32_t smem_u32(const void* p) {
    uint32_t a;
    asm("{ .reg .u64 t; cvta.to.shared.u64 t, %1; cvt.u32.u64 %0, t; }" : "=r"(a) : "l"(p));
    return a;
}

__device__ __forceinline__ void ldsm4(uint32_t* r, uint32_t addr) {
    asm volatile("ldmatrix.sync.aligned.m8n8.x4.shared.b16 {%0,%1,%2,%3}, [%4];"
                 : "=r"(r[0]), "=r"(r[1]), "=r"(r[2]), "=r"(r[3]) : "r"(addr));
}

__device__ __forceinline__ void mma16816(float* d, const uint32_t* a, const uint32_t* b) {
    asm volatile(
        "mma.sync.aligned.m16n8k16.row.col.f32.f16.f16.f32 "
        "{%0,%1,%2,%3}, {%4,%5,%6,%7}, {%8,%9}, {%0,%1,%2,%3};"
        : "+f"(d[0]), "+f"(d[1]), "+f"(d[2]), "+f"(d[3])
        : "r"(a[0]), "r"(a[1]), "r"(a[2]), "r"(a[3]), "r"(b[0]), "r"(b[1]));
}

#define CP_ASYNC16(dst, src) \
    asm volatile("cp.async.cg.shared.global [%0], [%1], 16;" :: "r"(dst), "l"(src))
#define CP_COMMIT()  asm volatile("cp.async.commit_group;")
#define CP_WAIT0()   asm volatile("cp.async.wait_group 0;")

// ---------------------------------------------------------------------------
// prep kernel: blocks 0..511 transpose+convert Wn / Wloc; blocks 512..575
// compute baseb partials over 64-d slices (deterministic, no atomics).
// 256 threads per block.
// ---------------------------------------------------------------------------
__global__ void prep_kernel(const float* __restrict__ W1,
                            const float* __restrict__ graph,
                            const float* __restrict__ locg) {
    __shared__ float sh[32 * 33];
    int bid = blockIdx.x;
    int tid = threadIdx.x;
    if (bid < 512) {
        int which = bid >> 8;
        int tile = bid & 255;
        const float* src = W1 + (which ? 1536 * 512 : 0);
        __half* dst = which ? g_WTloc : g_WTn;
        int d0 = (tile & 15) * 32, f0 = (tile >> 4) * 32;
        int tx = tid & 31, ty = tid >> 5;  // (32, 8)
#pragma unroll
        for (int i = 0; i < 32; i += 8)
            sh[(ty + i) * 33 + tx] = src[(size_t)(d0 + ty + i) * 512 + f0 + tx];
        __syncthreads();
#pragma unroll
        for (int i = 0; i < 32; i += 8)
            dst[(size_t)(f0 + ty + i) * 512 + d0 + tx] = __float2half_rn(sh[tx * 33 + ty + i]);
    } else {
        int idx = bid - 512;            // 0..63
        int b = idx >> 3, ds = idx & 7; // d-range ds*64..+64
        float* sg = sh;                 // 64 floats
        float* sl = sh + 64;
        if (tid < 64) {
            sg[tid] = graph[b * 512 + ds * 64 + tid];
            sl[tid] = locg[b * 512 + ds * 64 + tid];
        }
        __syncthreads();
        const float* Wg = W1 + (size_t)512 * 512;
        const float* Wl = W1 + (size_t)1024 * 512;
        float a0 = 0.f, a1 = 0.f;
#pragma unroll 4
        for (int d = 0; d < 64; ++d) {
            size_t row = (size_t)(ds * 64 + d) * 512;
            float g = sg[d], l = sl[d];
            a0 += g * Wg[row + tid] + l * Wl[row + tid];
            a1 += g * Wg[row + tid + 256] + l * Wl[row + tid + 256];
        }
        g_basebp[ds][b][tid] = a0;
        g_basebp[ds][b][tid + 256] = a1;
    }
}

// ---------------------------------------------------------------------------
// gemm kernel: fp16 mma.sync, CTA tile 128(M) x 256(N), K=512.
// 256 threads = 8 warps as 2(M) x 4(N); warp tile 64x64.
// MODE 0: A=node (M=4096),  B=WTn;   epi: g_base = acc + (b1 + sum basebp)
// MODE 1: A=loc  (M=65536), B=WTloc; epi: g_part[nc] = sum_f relu(acc+base)*w2
// blockIdx.x = N-chunk (0..1), blockIdx.y = M-tile.
// ---------------------------------------------------------------------------
template <int MODE>
__global__ void __launch_bounds__(256)
gemm_kernel(const float* __restrict__ A, const float* __restrict__ W2,
            const float* __restrict__ b1) {
    extern __shared__ char smem[];
    const uint32_t sb = smem_u32(smem);
    const int tid = threadIdx.x;
    const int lane = tid & 31, wid = tid >> 5;
    const int wm = wid & 1, wn = wid >> 1;     // 2(M) x 4(N)
    const int m0 = blockIdx.y * M_TILE;
    const int nc = blockIdx.x;
    const int n0 = nc * N_TILE;
    const __half* BT = (MODE == 0) ? g_WTn : g_WTloc;

    float* sbase = (float*)(smem + SM_SBASE);
    float* svec  = (float*)(smem + SM_SVEC);
    float* red   = (float*)(smem + SM_RED);

    // preload epilogue data (independent of mainloop)
    if (MODE == 1) {
        const float* gb = g_base + (size_t)(m0 >> 4) * 512 + n0;  // 8 rows x 256
        for (int i = tid; i < 2048; i += 256) {
            int r = i >> 8, c = i & 255;
            sbase[i] = gb[(size_t)r * 512 + c];
        }
        if (tid < 256) svec[tid] = W2[n0 + tid];
    } else {
        int b = m0 >> 9;
        float v = b1[n0 + tid];
#pragma unroll
        for (int s = 0; s < 8; s++) v += g_basebp[s][b][n0 + tid];
        svec[tid] = v;
    }

    const float*  gA = A + (size_t)m0 * 512;
    const __half* gB = BT + (size_t)n0 * 512;

    // per-thread load indices
    const int ar = (tid >> 4), ac4 = (tid & 15);   // A: 16 rows/iter, 8 iters
    const int br = (tid >> 3), bc16 = (tid & 7);   // B: 32 rows/iter, 8 iters

    float4 va[8];

    auto ldA = [&](int c) {
        const float* p = gA + c * K_CHUNK;
#pragma unroll
        for (int i = 0; i < 8; i++) {
            int r = ar + i * 16;
            va[i] = *(const float4*)(p + (size_t)r * 512 + ac4 * 4);
        }
    };
    auto stA = [&](uint32_t sA) {
#pragma unroll
        for (int i = 0; i < 8; i++) {
            int r = ar + i * 16;
            uint32_t ad = sA + r * 128 + ((ac4 * 8) ^ ((r & 7) * 16));
            __half2 h0 = __floats2half2_rn(va[i].x, va[i].y);
            __half2 h1 = __floats2half2_rn(va[i].z, va[i].w);
            uint32_t u0 = *(uint32_t*)&h0, u1 = *(uint32_t*)&h1;
            asm volatile("st.shared.v2.b32 [%0], {%1,%2};" :: "r"(ad), "r"(u0), "r"(u1));
        }
    };
    auto cpB = [&](int c, uint32_t sB) {
        const __half* p = gB + c * K_CHUNK;
#pragma unroll
        for (int i = 0; i < 8; i++) {
            int r = br + i * 32;
            uint32_t dst = sB + r * 128 + ((bc16 * 16) ^ ((r & 7) * 16));
            CP_ASYNC16(dst, p + (size_t)r * 512 + bc16 * 8);
        }
        CP_COMMIT();
    };

    // ldmatrix lane address precompute
    uint32_t aRB[4], aXO[4];
    const uint32_t aSel = (lane >> 4) * 16;
#pragma unroll
    for (int i = 0; i < 4; i++) {
        int r = wm * 64 + i * 16 + (lane & 15);
        aRB[i] = r * 128;
        aXO[i] = (r & 7) * 16;
    }
    uint32_t bRB[4], bXO[4];
    const uint32_t bSel = ((lane >> 3) & 1) * 16;
#pragma unroll
    for (int j = 0; j < 4; j++) {
        int r = wn * 64 + j * 16 + ((lane >> 4) << 3) + (lane & 7);
        bRB[j] = r * 128;
        bXO[j] = (r & 7) * 16;
    }

    float acc[4][8][4];
#pragma unroll
    for (int i = 0; i < 4; i++)
#pragma unroll
        for (int j = 0; j < 8; j++)
#pragma unroll
            for (int q = 0; q < 4; q++) acc[i][j][q] = 0.f;

    // prologue
    ldA(0);
    cpB(0, sb + 16384);
    stA(sb);
    CP_WAIT0();
    __syncthreads();

    int buf = 0;
#pragma unroll 1
    for (int c = 0; c < KCHUNKS; ++c) {
        const uint32_t sA = sb + buf * STG_BYTES;
        const uint32_t sBs = sA + 16384;
        const uint32_t oA = sb + (buf ^ 1) * STG_BYTES;
        if (c + 1 < KCHUNKS) {
            ldA(c + 1);               // LDGs in flight under the mma below
            cpB(c + 1, oA + 16384);
        }
#pragma unroll
        for (int ks = 0; ks < 4; ks++) {
            uint32_t af[4][4], bf[4][4];
            const uint32_t kc = ks * 32;
#pragma unroll
            for (int i = 0; i < 4; i++)
                ldsm4(af[i], sA + aRB[i] + ((kc | aSel) ^ aXO[i]));
#pragma unroll
            for (int j = 0; j < 4; j++)
                ldsm4(bf[j], sBs + bRB[j] + ((kc | bSel) ^ bXO[j]));
#pragma unroll
            for (int i = 0; i < 4; i++)
#pragma unroll
                for (int j = 0; j < 8; j++)
                    mma16816(acc[i][j], af[i], &bf[j >> 1][(j & 1) * 2]);
        }
        if (c + 1 < KCHUNKS) {
            stA(oA);
            CP_WAIT0();
        }
        __syncthreads();
        buf ^= 1;
    }

    // ---------------- epilogue ----------------
    const int t4 = lane >> 2;
    if (MODE == 0) {
#pragma unroll
        for (int i = 0; i < 4; i++) {
            int rL = wm * 64 + i * 16 + t4;
#pragma unroll
            for (int j = 0; j < 8; j++) {
                int c0 = wn * 64 + j * 8 + 2 * (lane & 3);
                float b0 = svec[c0], b1v = svec[c0 + 1];
                float2 v0 = make_float2(acc[i][j][0] + b0, acc[i][j][1] + b1v);
                float2 v1 = make_float2(acc[i][j][2] + b0, acc[i][j][3] + b1v);
                *(float2*)(g_base + (size_t)(m0 + rL) * 512 + n0 + c0) = v0;
                *(float2*)(g_base + (size_t)(m0 + rL + 8) * 512 + n0 + c0) = v1;
            }
        }
    } else {
        float psum[8];
#pragma unroll
        for (int ii = 0; ii < 8; ii++) psum[ii] = 0.f;
#pragma unroll
        for (int i = 0; i < 4; i++) {
            int rL0 = wm * 64 + i * 16 + t4;
            int br0 = rL0 >> 4;
            int br1 = (rL0 + 8) >> 4;
#pragma unroll
            for (int j = 0; j < 8; j++) {
                int c0 = wn * 64 + j * 8 + 2 * (lane & 3);
                float w0 = svec[c0], w1 = svec[c0 + 1];
                float b00 = sbase[br0 * 256 + c0], b01 = sbase[br0 * 256 + c0 + 1];
                float b10 = sbase[br1 * 256 + c0], b11 = sbase[br1 * 256 + c0 + 1];
                psum[i * 2 + 0] += fmaxf(acc[i][j][0] + b00, 0.f) * w0
                                 + fmaxf(acc[i][j][1] + b01, 0.f) * w1;
                psum[i * 2 + 1] += fmaxf(acc[i][j][2] + b10, 0.f) * w0
                                 + fmaxf(acc[i][j][3] + b11, 0.f) * w1;
            }
        }
#pragma unroll
        for (int ii = 0; ii < 8; ii++) {
            psum[ii] += __shfl_xor_sync(0xffffffffu, psum[ii], 1);
            psum[ii] += __shfl_xor_sync(0xffffffffu, psum[ii], 2);
        }
        if ((lane & 3) == 0) {
#pragma unroll
            for (int ii = 0; ii < 8; ii++) {
                int row = wm * 64 + (ii >> 1) * 16 + (ii & 1) * 8 + t4;
                red[wn * 128 + row] = psum[ii];
            }
        }
        __syncthreads();
        if (tid < 128)
            g_part[nc][m0 + tid] = red[tid] + red[128 + tid] + red[256 + tid] + red[384 + tid];
    }
}

// ---------------------------------------------------------------------------
// reduce: out = sum of 2 partials + b2
// ---------------------------------------------------------------------------
__global__ void reduce_kernel(const float* __restrict__ b2, float* __restrict__ out) {
    int i = blockIdx.x * 256 + threadIdx.x;
    out[i] = g_part[0][i] + g_part[1][i] + b2[0];
}

// ---------------------------------------------------------------------------
// Launch
// ---------------------------------------------------------------------------
extern "C" void kernel_launch(void* const* d_in, const int* in_sizes, int n_in,
                              void* d_out, int out_size) {
    const float* node  = (const float*)d_in[0];  // (8, 512, 512)
    const float* loc   = (const float*)d_in[1];  // (8, 512, 16, 512)
    const float* graph = (const float*)d_in[2];  // (8, 512)
    const float* locg  = (const float*)d_in[3];  // (8, 512)
    const float* W1    = (const float*)d_in[4];  // (2048, 512)
    const float* b1    = (const float*)d_in[5];  // (512,)
    const float* W2    = (const float*)d_in[6];  // (512, 1)
    const float* b2    = (const float*)d_in[7];  // (1,)
    float* out = (float*)d_out;                  // (8, 8192)
    (void)in_sizes; (void)n_in; (void)out_size;

    cudaFuncSetAttribute(gemm_kernel<0>, cudaFuncAttributeMaxDynamicSharedMemorySize, SMEM_BYTES);
    cudaFuncSetAttribute(gemm_kernel<1>, cudaFuncAttributeMaxDynamicSharedMemorySize, SMEM_BYTES);

    prep_kernel<<<576, 256>>>(W1, graph, locg);
    gemm_kernel<0><<<dim3(2, 32), 256, SMEM_BYTES>>>(node, nullptr, b1);
    gemm_kernel<1><<<dim3(2, 512), 256, SMEM_BYTES>>>(loc, W2, nullptr);
    reduce_kernel<<<256, 256>>>(b2, out);
}